// round 7
// baseline (speedup 1.0000x reference)
#include <cuda_runtime.h>
#include <cuda_fp16.h>
#include <math.h>

#define B_   64
#define L_   32
#define D_   1024
#define DFF  2048
#define K_   128
#define N_   256

// ---------------- scratch (no allocations allowed) ----------------
__device__ float g_A[N_ * N_];
__device__ float g_W[N_ * K_ * K_];
__device__ float g_wpart[8][N_ * K_];
__device__ float g_xr[B_ * N_ * K_];
__device__ float g_xloc[B_ * N_ * K_];
__device__ float g_xln[B_ * K_ * N_];
__device__ float g_xglob[B_ * K_ * N_];
__device__ float g_mixed[B_ * L_ * D_];
__device__ float g_G[B_ * L_ * DFF];
__device__ float g_U[B_ * L_ * DFF];
__device__ float g_H[B_ * L_ * DFF];
__device__ float g_ffn[B_ * L_ * D_];

// ---------------- helpers ----------------
__device__ __forceinline__ void blockReduce2_256(float& s1, float& s2) {
    __shared__ float sh1[8], sh2[8];
    int t = threadIdx.x;
    #pragma unroll
    for (int o = 16; o > 0; o >>= 1) {
        s1 += __shfl_xor_sync(0xffffffffu, s1, o);
        s2 += __shfl_xor_sync(0xffffffffu, s2, o);
    }
    if ((t & 31) == 0) { sh1[t >> 5] = s1; sh2[t >> 5] = s2; }
    __syncthreads();
    float a = 0.f, b = 0.f;
    #pragma unroll
    for (int w = 0; w < 8; w++) { a += sh1[w]; b += sh2[w]; }
    s1 = a; s2 = b;
    __syncthreads();
}

// pack two fp32 into fp16x2 (x0 -> low half)
__device__ __forceinline__ unsigned pack16(float x0, float x1) {
    unsigned h;
    asm("cvt.rn.f16x2.f32 %0, %1, %2;" : "=r"(h) : "f"(x1), "f"(x0));
    return h;
}

__device__ __forceinline__ void mma16816(float* c, const unsigned* a, unsigned b0, unsigned b1) {
    asm volatile(
        "mma.sync.aligned.m16n8k16.row.col.f32.f16.f16.f32 "
        "{%0,%1,%2,%3}, {%4,%5,%6,%7}, {%8,%9}, {%0,%1,%2,%3};"
        : "+f"(c[0]), "+f"(c[1]), "+f"(c[2]), "+f"(c[3])
        : "r"(a[0]), "r"(a[1]), "r"(a[2]), "r"(a[3]), "r"(b0), "r"(b1));
}

// ---------------- K0: A = A_logits / max(||col||, eps) ----------------
__global__ void k_prepA(const float* __restrict__ Al) {
    int j = blockIdx.x;
    int i = threadIdx.x;
    float v = Al[i * N_ + j];
    float s1 = v * v, s2 = 0.f;
    blockReduce2_256(s1, s2);
    float inv = 1.f / fmaxf(sqrtf(s1), 1e-12f);
    g_A[i * N_ + j] = v * inv;
}

// ---------------- prepW ----------------
__global__ void k_prepW1(const float* __restrict__ W1, const float* __restrict__ WV) {
    int tt = blockIdx.x;        // 16 t-tiles of 16
    int is = blockIdx.y;        // 8 i-slices of 16
    int o  = threadIdx.x;       // 128
    __shared__ float w1s[16][8];
    w1s[o >> 3][o & 7] = W1[(tt * 16 + (o >> 3)) * 8 + (o & 7)];
    __syncthreads();
    float ss[16];
    #pragma unroll
    for (int tl = 0; tl < 16; tl++) ss[tl] = 0.f;
    for (int ii = 0; ii < 16; ii++) {
        int i = is * 16 + ii;
        float wv[8];
        #pragma unroll
        for (int k = 0; k < 8; k++) wv[k] = WV[((size_t)k * K_ + i) * K_ + o];
        #pragma unroll
        for (int tl = 0; tl < 16; tl++) {
            float wl = 0.f;
            #pragma unroll
            for (int k = 0; k < 8; k++) wl += w1s[tl][k] * wv[k];
            ss[tl] += wl * wl;
            g_W[((size_t)(tt * 16 + tl) * K_ + i) * K_ + o] = wl;
        }
    }
    #pragma unroll
    for (int tl = 0; tl < 16; tl++)
        g_wpart[is][(tt * 16 + tl) * K_ + o] = ss[tl];
}

__global__ void k_prepW2() {
    int t  = blockIdx.x;        // 256
    int ig = blockIdx.y;        // 8 i-groups of 16
    int o  = threadIdx.x;       // 128
    float ss = 0.f;
    #pragma unroll
    for (int s = 0; s < 8; s++) ss += g_wpart[s][t * K_ + o];
    float inv = 1.f / fmaxf(sqrtf(ss), 1e-12f);
    #pragma unroll
    for (int i = ig * 16; i < ig * 16 + 16; i++)
        g_W[((size_t)t * K_ + i) * K_ + o] *= inv;
}

// ---------------- K2: xr = LN128( x + LN_D(y) ) ----------------
__global__ void k_xr(const float* __restrict__ x, const float* __restrict__ y,
                     const float* __restrict__ nyg, const float* __restrict__ nyb,
                     const float* __restrict__ kn1g, const float* __restrict__ kn1b) {
    int row = blockIdx.x;
    int t = threadIdx.x;
    const float* yr = y + (size_t)row * D_;
    const float* xp = x + (size_t)row * D_;
    float yv[4];
    float s1 = 0.f, s2 = 0.f;
    #pragma unroll
    for (int e = 0; e < 4; e++) {
        float v = yr[t * 4 + e];
        yv[e] = v; s1 += v; s2 += v * v;
    }
    blockReduce2_256(s1, s2);
    float m = s1 * (1.f / D_);
    float var = s2 * (1.f / D_) - m * m;
    float rs = rsqrtf(var + 1e-5f);
    float kin[4];
    float ls1 = 0.f, ls2 = 0.f;
    #pragma unroll
    for (int e = 0; e < 4; e++) {
        int d = t * 4 + e;
        float ny = (yv[e] - m) * rs * nyg[d] + nyb[d];
        float kv = xp[d] + ny;
        kin[e] = kv; ls1 += kv; ls2 += kv * kv;
    }
    #pragma unroll
    for (int o = 16; o > 0; o >>= 1) {
        ls1 += __shfl_xor_sync(0xffffffffu, ls1, o);
        ls2 += __shfl_xor_sync(0xffffffffu, ls2, o);
    }
    float lm = ls1 * (1.f / 128.f);
    float lv = ls2 * (1.f / 128.f) - lm * lm;
    float lrs = rsqrtf(lv + 1e-5f);
    #pragma unroll
    for (int e = 0; e < 4; e++) {
        int d = t * 4 + e;
        int i = d & 127;
        g_xr[(size_t)row * D_ + d] = (kin[e] - lm) * lrs * kn1g[i] + kn1b[i];
    }
}

// ---------------- K3: x_local[b,n,o] = sum_i xr[b,n,i] * W[n,i,o] ----------------
#define BG 32
__global__ void k_xlocal() {
    int n  = blockIdx.x;
    int b0 = blockIdx.y * BG;
    int o  = threadIdx.x;        // 128
    __shared__ float xs[BG][K_];
    #pragma unroll 8
    for (int bb = 0; bb < BG; bb++)
        xs[bb][o] = g_xr[((size_t)(b0 + bb) * N_ + n) * K_ + o];
    __syncthreads();
    float acc[BG];
    #pragma unroll
    for (int bb = 0; bb < BG; bb++) acc[bb] = 0.f;
    const float* Wn = g_W + (size_t)n * K_ * K_;
    for (int i0 = 0; i0 < K_; i0 += 4) {
        float w0 = Wn[(i0 + 0) * K_ + o];
        float w1 = Wn[(i0 + 1) * K_ + o];
        float w2 = Wn[(i0 + 2) * K_ + o];
        float w3 = Wn[(i0 + 3) * K_ + o];
        #pragma unroll
        for (int bb = 0; bb < BG; bb++) {
            float4 xv = *(const float4*)&xs[bb][i0];
            acc[bb] += xv.x * w0 + xv.y * w1 + xv.z * w2 + xv.w * w3;
        }
    }
    #pragma unroll 8
    for (int bb = 0; bb < BG; bb++)
        g_xloc[((size_t)(b0 + bb) * N_ + n) * K_ + o] = acc[bb];
}

// ---------------- K4a: transpose + LN over N (kn2), 32 k per block ----------------
__global__ void k_trln(const float* __restrict__ kn2g, const float* __restrict__ kn2b) {
    int k0 = blockIdx.x * 32;
    int b  = blockIdx.y;
    int t  = threadIdx.x;
    __shared__ float tr[32][264];
    __shared__ float mm[32], rr[32];
    for (int q = t; q < 2048; q += 256) {
        int n = q >> 3, f = q & 7;
        float4 v = *(const float4*)&g_xloc[((size_t)b * N_ + n) * K_ + k0 + f * 4];
        tr[f * 4 + 0][n] = v.x; tr[f * 4 + 1][n] = v.y;
        tr[f * 4 + 2][n] = v.z; tr[f * 4 + 3][n] = v.w;
    }
    __syncthreads();
    int k = t >> 3, s = t & 7;
    float s1 = 0.f, s2 = 0.f;
    #pragma unroll 8
    for (int j = 0; j < 32; j++) {
        float v = tr[k][s + 8 * j];
        s1 += v; s2 += v * v;
    }
    #pragma unroll
    for (int off = 4; off > 0; off >>= 1) {
        s1 += __shfl_xor_sync(0xffffffffu, s1, off);
        s2 += __shfl_xor_sync(0xffffffffu, s2, off);
    }
    if (s == 0) {
        float m = s1 * (1.f / N_);
        float var = s2 * (1.f / N_) - m * m;
        mm[k] = m; rr[k] = rsqrtf(var + 1e-5f);
    }
    __syncthreads();
    int n2 = t;
    float gn = kn2g[n2], bn = kn2b[n2];
    #pragma unroll 4
    for (int kk = 0; kk < 32; kk++) {
        float v = (tr[kk][n2] - mm[kk]) * rr[kk] * gn + bn;
        g_xln[((size_t)b * K_ + k0 + kk) * N_ + n2] = v;
    }
}

// ---------------- K4b: x_global = x_ln @ A (32 k rows per block) ----------------
__global__ void k_xglob() {
    int kg = blockIdx.x;
    int b  = blockIdx.y;
    int t  = threadIdx.x;
    __shared__ float rows[32][256];
    for (int q = t; q < 2048; q += 256) {
        int kk = q >> 6, m4 = (q & 63) * 4;
        *(float4*)&rows[kk][m4] =
            *(const float4*)&g_xln[((size_t)b * K_ + kg * 32 + kk) * N_ + m4];
    }
    __syncthreads();
    float acc[32];
    #pragma unroll
    for (int kk = 0; kk < 32; kk++) acc[kk] = 0.f;
    int m = t;
    for (int nn = 0; nn < N_; nn += 4) {
        float a0 = g_A[(nn + 0) * N_ + m];
        float a1 = g_A[(nn + 1) * N_ + m];
        float a2 = g_A[(nn + 2) * N_ + m];
        float a3 = g_A[(nn + 3) * N_ + m];
        #pragma unroll
        for (int kk = 0; kk < 32; kk++) {
            float4 rv = *(const float4*)&rows[kk][nn];
            acc[kk] += rv.x * a0 + rv.y * a1 + rv.z * a2 + rv.w * a3;
        }
    }
    #pragma unroll 4
    for (int kk = 0; kk < 32; kk++)
        g_xglob[((size_t)b * K_ + kg * 32 + kk) * N_ + m] = acc[kk];
}

// ---------------- K5: mixed = LN( x + 0.5*rule + 0.5*kron , n1) ----------------
__global__ void k_mixed(const float* __restrict__ x,
                        const float* __restrict__ n1g, const float* __restrict__ n1b) {
    int row = blockIdx.x;
    int b = row >> 5, l = row & 31;
    int t = threadIdx.x;
    float v[4];
    float s1 = 0.f, s2 = 0.f;
    #pragma unroll
    for (int e = 0; e < 4; e++) {
        int d = t * 4 + e;
        float rule = x[((size_t)b * L_ + (d >> 5)) * D_ + l * 32 + (d & 31)];
        float kron = g_xglob[(size_t)row * D_ + d];
        float xv   = x[(size_t)row * D_ + d];
        float val = xv + 0.5f * rule + 0.5f * kron;
        v[e] = val; s1 += val; s2 += val * val;
    }
    blockReduce2_256(s1, s2);
    float m = s1 * (1.f / D_);
    float var = s2 * (1.f / D_) - m * m;
    float rs = rsqrtf(var + 1e-5f);
    #pragma unroll
    for (int e = 0; e < 4; e++) {
        int d = t * 4 + e;
        g_mixed[(size_t)row * D_ + d] = (v[e] - m) * rs * n1g[d] + n1b[d];
    }
}

// ---------------- tensor-core GEMM, plain fp16 single product ----------------
// mode 0: A = g_mixed(l), K=1024, width=DFF, out = z ? g_U : g_G, W = z ? W1 : W0
// mode 1: A = g_H(l),     K=2048, width=D_,  out = g_ffn,          W = W0
__global__ __launch_bounds__(256, 3) void k_gemm(const float* __restrict__ W0,
                                                 const float* __restrict__ W1,
                                                 int mode) {
    __shared__ unsigned Ah[16][72];   // [kpair][m] fp16x2
    __shared__ unsigned Bh[16][136];  // [kpair][n] fp16x2

    int l   = blockIdx.x;
    int nt0 = blockIdx.y * 128;
    int t   = threadIdx.x;

    const float* Ap; long lda; int Kdim, width;
    const float* Bp; float* Op;
    if (mode == 0) {
        Ap = g_mixed + (size_t)l * D_;  lda = (long)L_ * D_;  Kdim = D_;  width = DFF;
        const float* Wsel = blockIdx.z ? W1 : W0;
        Bp = Wsel + (size_t)l * D_ * DFF + nt0;
        Op = (blockIdx.z ? g_U : g_G) + (size_t)l * DFF + nt0;
    } else {
        Ap = g_H + (size_t)l * DFF;     lda = (long)L_ * DFF; Kdim = DFF; width = D_;
        Bp = W0 + (size_t)l * DFF * D_ + nt0;
        Op = g_ffn + (size_t)l * D_ + nt0;
    }

    int lane = t & 31, wid = t >> 5;
    int g = lane >> 2, tg = lane & 3;
    int wm = (wid & 1) * 32;          // 2 warps over M=64
    int wn = (wid >> 1) * 32;         // 4 warps over N=128

    float acc[2][4][4];
    #pragma unroll
    for (int mt = 0; mt < 2; mt++)
        #pragma unroll
        for (int nt = 0; nt < 4; nt++)
            #pragma unroll
            for (int e = 0; e < 4; e++) acc[mt][nt][e] = 0.f;

    for (int k0 = 0; k0 < Kdim; k0 += 32) {
        // A tile: 64 x 32 fp32 -> fp16 [kp][m]
        #pragma unroll
        for (int q = t; q < 512; q += 256) {
            int m = q >> 3, f4 = q & 7;
            float4 v = *(const float4*)(Ap + (size_t)m * lda + k0 + f4 * 4);
            Ah[f4 * 2][m]     = pack16(v.x, v.y);
            Ah[f4 * 2 + 1][m] = pack16(v.z, v.w);
        }
        // B tile: 32 x 128 fp32 -> fp16, pair consecutive k rows
        #pragma unroll
        for (int q = t; q < 512; q += 256) {
            int kp = q >> 5, n4 = (q & 31) * 4;
            const float* bp0 = Bp + (size_t)(k0 + 2 * kp) * width + n4;
            float4 u0 = *(const float4*)bp0;
            float4 u1 = *(const float4*)(bp0 + width);
            Bh[kp][n4 + 0] = pack16(u0.x, u1.x);
            Bh[kp][n4 + 1] = pack16(u0.y, u1.y);
            Bh[kp][n4 + 2] = pack16(u0.z, u1.z);
            Bh[kp][n4 + 3] = pack16(u0.w, u1.w);
        }
        __syncthreads();

        #pragma unroll
        for (int s = 0; s < 2; s++) {
            int kp0 = s * 8 + tg, kp1 = kp0 + 4;
            unsigned afh[2][4];
            #pragma unroll
            for (int mt = 0; mt < 2; mt++) {
                int r0 = wm + mt * 16 + g, r1 = r0 + 8;
                afh[mt][0] = Ah[kp0][r0]; afh[mt][1] = Ah[kp0][r1];
                afh[mt][2] = Ah[kp1][r0]; afh[mt][3] = Ah[kp1][r1];
            }
            #pragma unroll
            for (int nt = 0; nt < 4; nt++) {
                int cn = wn + nt * 8 + g;
                unsigned bh0 = Bh[kp0][cn], bh1 = Bh[kp1][cn];
                #pragma unroll
                for (int mt = 0; mt < 2; mt++)
                    mma16816(acc[mt][nt], afh[mt], bh0, bh1);
            }
        }
        __syncthreads();
    }

    long ostride = (long)L_ * width;
    #pragma unroll
    for (int mt = 0; mt < 2; mt++) {
        int r0 = wm + mt * 16 + g;
        #pragma unroll
        for (int nt = 0; nt < 4; nt++) {
            int c = wn + nt * 8 + tg * 2;
            float* p0 = Op + (size_t)r0 * ostride + c;
            float* p1 = Op + (size_t)(r0 + 8) * ostride + c;
            *(float2*)p0 = make_float2(acc[mt][nt][0], acc[mt][nt][1]);
            *(float2*)p1 = make_float2(acc[mt][nt][2], acc[mt][nt][3]);
        }
    }
}

// ---------------- K6b: H = silu(G) * U ----------------
__global__ void k_act() {
    int idx = blockIdx.x * 256 + threadIdx.x;
    float4 g = ((const float4*)g_G)[idx];
    float4 u = ((const float4*)g_U)[idx];
    float4 h;
    h.x = g.x / (1.f + expf(-g.x)) * u.x;
    h.y = g.y / (1.f + expf(-g.y)) * u.y;
    h.z = g.z / (1.f + expf(-g.z)) * u.z;
    h.w = g.w / (1.f + expf(-g.w)) * u.w;
    ((float4*)g_H)[idx] = h;
}

// ---------------- K8: out = LN(mixed+ffn, n2); y_out = y + ffn ----------------
__global__ void k_final(const float* __restrict__ y,
                        const float* __restrict__ n2g, const float* __restrict__ n2b,
                        float* __restrict__ out) {
    int row = blockIdx.x;
    int t = threadIdx.x;
    float v[4], fv[4];
    float s1 = 0.f, s2 = 0.f;
    #pragma unroll
    for (int e = 0; e < 4; e++) {
        int d = t * 4 + e;
        size_t idx = (size_t)row * D_ + d;
        float f = g_ffn[idx];
        float val = g_mixed[idx] + f;
        v[e] = val; fv[e] = f; s1 += val; s2 += val * val;
    }
    blockReduce2_256(s1, s2);
    float m = s1 * (1.f / D_);
    float var = s2 * (1.f / D_) - m * m;
    float rs = rsqrtf(var + 1e-5f);
    #pragma unroll
    for (int e = 0; e < 4; e++) {
        int d = t * 4 + e;
        size_t idx = (size_t)row * D_ + d;
        out[idx] = (v[e] - m) * rs * n2g[d] + n2b[d];
        out[(size_t)B_ * L_ * D_ + idx] = y[idx] + fv[e];
    }
}

// ---------------- launch ----------------
extern "C" void kernel_launch(void* const* d_in, const int* in_sizes, int n_in,
                              void* d_out, int out_size) {
    const float* x       = (const float*)d_in[0];
    const float* y       = (const float*)d_in[1];
    const float* A_log   = (const float*)d_in[2];
    const float* W_1     = (const float*)d_in[3];
    const float* W_V     = (const float*)d_in[4];
    const float* kn1_g   = (const float*)d_in[5];
    const float* kn1_b   = (const float*)d_in[6];
    const float* kn2_g   = (const float*)d_in[7];
    const float* kn2_b   = (const float*)d_in[8];
    const float* W_gate  = (const float*)d_in[9];
    const float* W_up    = (const float*)d_in[10];
    const float* W_down  = (const float*)d_in[11];
    const float* ny_g    = (const float*)d_in[12];
    const float* ny_b    = (const float*)d_in[13];
    const float* n1_g    = (const float*)d_in[14];
    const float* n1_b    = (const float*)d_in[15];
    const float* n2_g    = (const float*)d_in[16];
    const float* n2_b    = (const float*)d_in[17];
    float* out = (float*)d_out;

    k_prepA<<<N_, 256>>>(A_log);
    k_prepW1<<<dim3(16, 8), 128>>>(W_1, W_V);
    k_prepW2<<<dim3(N_, 8), 128>>>();
    k_xr<<<B_ * L_, 256>>>(x, y, ny_g, ny_b, kn1_g, kn1_b);
    k_xlocal<<<dim3(N_, B_ / BG), 128>>>();
    k_trln<<<dim3(4, B_), 256>>>(kn2_g, kn2_b);
    k_xglob<<<dim3(4, B_), 256>>>();
    k_mixed<<<B_ * L_, 256>>>(x, n1_g, n1_b);
    k_gemm<<<dim3(L_, DFF / 128, 2), 256>>>(W_gate, W_up, 0);
    k_act<<<(B_ * L_ * DFF) / (256 * 4), 256>>>();
    k_gemm<<<dim3(L_, D_ / 128, 1), 256>>>(W_down, W_down, 1);
    k_final<<<B_ * L_, 256>>>(y, n2_g, n2_b, out);
}

// round 8
// speedup vs baseline: 1.2751x; 1.2751x over previous
#include <cuda_runtime.h>
#include <cuda_fp16.h>
#include <math.h>

#define B_   64
#define L_   32
#define D_   1024
#define DFF  2048
#define K_   128
#define N_   256

// ---------------- scratch (no allocations allowed) ----------------
__device__ float g_A[N_ * N_];
__device__ float g_W[N_ * K_ * K_];
__device__ float g_wpart[8][N_ * K_];
__device__ float g_xr[B_ * N_ * K_];
__device__ float g_xloc[B_ * N_ * K_];
__device__ float g_xln[B_ * K_ * N_];
__device__ float g_xglob[B_ * K_ * N_];
__device__ float g_mixed[B_ * L_ * D_];
__device__ float g_G[B_ * L_ * DFF];
__device__ float g_U[B_ * L_ * DFF];
__device__ float g_H[B_ * L_ * DFF];
__device__ float g_ffn[B_ * L_ * D_];

// ---------------- helpers ----------------
__device__ __forceinline__ void blockReduce2_256(float& s1, float& s2) {
    __shared__ float sh1[8], sh2[8];
    int t = threadIdx.x;
    #pragma unroll
    for (int o = 16; o > 0; o >>= 1) {
        s1 += __shfl_xor_sync(0xffffffffu, s1, o);
        s2 += __shfl_xor_sync(0xffffffffu, s2, o);
    }
    if ((t & 31) == 0) { sh1[t >> 5] = s1; sh2[t >> 5] = s2; }
    __syncthreads();
    float a = 0.f, b = 0.f;
    #pragma unroll
    for (int w = 0; w < 8; w++) { a += sh1[w]; b += sh2[w]; }
    s1 = a; s2 = b;
    __syncthreads();
}

// pack two fp32 into fp16x2 (x0 -> low half)
__device__ __forceinline__ unsigned pack16(float x0, float x1) {
    unsigned h;
    asm("cvt.rn.f16x2.f32 %0, %1, %2;" : "=r"(h) : "f"(x1), "f"(x0));
    return h;
}

__device__ __forceinline__ void mma16816(float* c, const unsigned* a, unsigned b0, unsigned b1) {
    asm volatile(
        "mma.sync.aligned.m16n8k16.row.col.f32.f16.f16.f32 "
        "{%0,%1,%2,%3}, {%4,%5,%6,%7}, {%8,%9}, {%0,%1,%2,%3};"
        : "+f"(c[0]), "+f"(c[1]), "+f"(c[2]), "+f"(c[3])
        : "r"(a[0]), "r"(a[1]), "r"(a[2]), "r"(a[3]), "r"(b0), "r"(b1));
}

// ---------------- K0: A = A_logits / max(||col||, eps) ----------------
__global__ void k_prepA(const float* __restrict__ Al) {
    int j = blockIdx.x;
    int i = threadIdx.x;
    float v = Al[i * N_ + j];
    float s1 = v * v, s2 = 0.f;
    blockReduce2_256(s1, s2);
    float inv = 1.f / fmaxf(sqrtf(s1), 1e-12f);
    g_A[i * N_ + j] = v * inv;
}

// ---------------- prepW ----------------
__global__ void k_prepW1(const float* __restrict__ W1, const float* __restrict__ WV) {
    int tt = blockIdx.x;        // 16 t-tiles of 16
    int is = blockIdx.y;        // 8 i-slices of 16
    int o  = threadIdx.x;       // 128
    __shared__ float w1s[16][8];
    w1s[o >> 3][o & 7] = W1[(tt * 16 + (o >> 3)) * 8 + (o & 7)];
    __syncthreads();
    float ss[16];
    #pragma unroll
    for (int tl = 0; tl < 16; tl++) ss[tl] = 0.f;
    for (int ii = 0; ii < 16; ii++) {
        int i = is * 16 + ii;
        float wv[8];
        #pragma unroll
        for (int k = 0; k < 8; k++) wv[k] = WV[((size_t)k * K_ + i) * K_ + o];
        #pragma unroll
        for (int tl = 0; tl < 16; tl++) {
            float wl = 0.f;
            #pragma unroll
            for (int k = 0; k < 8; k++) wl += w1s[tl][k] * wv[k];
            ss[tl] += wl * wl;
            g_W[((size_t)(tt * 16 + tl) * K_ + i) * K_ + o] = wl;
        }
    }
    #pragma unroll
    for (int tl = 0; tl < 16; tl++)
        g_wpart[is][(tt * 16 + tl) * K_ + o] = ss[tl];
}

__global__ void k_prepW2() {
    int t  = blockIdx.x;        // 256
    int ig = blockIdx.y;        // 8 i-groups of 16
    int o  = threadIdx.x;       // 128
    float ss = 0.f;
    #pragma unroll
    for (int s = 0; s < 8; s++) ss += g_wpart[s][t * K_ + o];
    float inv = 1.f / fmaxf(sqrtf(ss), 1e-12f);
    #pragma unroll
    for (int i = ig * 16; i < ig * 16 + 16; i++)
        g_W[((size_t)t * K_ + i) * K_ + o] *= inv;
}

// ---------------- K2: xr = LN128( x + LN_D(y) ) ----------------
__global__ void k_xr(const float* __restrict__ x, const float* __restrict__ y,
                     const float* __restrict__ nyg, const float* __restrict__ nyb,
                     const float* __restrict__ kn1g, const float* __restrict__ kn1b) {
    int row = blockIdx.x;
    int t = threadIdx.x;
    const float* yr = y + (size_t)row * D_;
    const float* xp = x + (size_t)row * D_;
    float yv[4];
    float s1 = 0.f, s2 = 0.f;
    #pragma unroll
    for (int e = 0; e < 4; e++) {
        float v = yr[t * 4 + e];
        yv[e] = v; s1 += v; s2 += v * v;
    }
    blockReduce2_256(s1, s2);
    float m = s1 * (1.f / D_);
    float var = s2 * (1.f / D_) - m * m;
    float rs = rsqrtf(var + 1e-5f);
    float kin[4];
    float ls1 = 0.f, ls2 = 0.f;
    #pragma unroll
    for (int e = 0; e < 4; e++) {
        int d = t * 4 + e;
        float ny = (yv[e] - m) * rs * nyg[d] + nyb[d];
        float kv = xp[d] + ny;
        kin[e] = kv; ls1 += kv; ls2 += kv * kv;
    }
    #pragma unroll
    for (int o = 16; o > 0; o >>= 1) {
        ls1 += __shfl_xor_sync(0xffffffffu, ls1, o);
        ls2 += __shfl_xor_sync(0xffffffffu, ls2, o);
    }
    float lm = ls1 * (1.f / 128.f);
    float lv = ls2 * (1.f / 128.f) - lm * lm;
    float lrs = rsqrtf(lv + 1e-5f);
    #pragma unroll
    for (int e = 0; e < 4; e++) {
        int d = t * 4 + e;
        int i = d & 127;
        g_xr[(size_t)row * D_ + d] = (kin[e] - lm) * lrs * kn1g[i] + kn1b[i];
    }
}

// ---------------- K3: x_local[b,n,o] = sum_i xr[b,n,i] * W[n,i,o] ----------------
#define BG 32
__global__ void k_xlocal() {
    int n  = blockIdx.x;
    int b0 = blockIdx.y * BG;
    int o  = threadIdx.x;        // 128
    __shared__ float xs[BG][K_];
    #pragma unroll 8
    for (int bb = 0; bb < BG; bb++)
        xs[bb][o] = g_xr[((size_t)(b0 + bb) * N_ + n) * K_ + o];
    __syncthreads();
    float acc[BG];
    #pragma unroll
    for (int bb = 0; bb < BG; bb++) acc[bb] = 0.f;
    const float* Wn = g_W + (size_t)n * K_ * K_;
    for (int i0 = 0; i0 < K_; i0 += 4) {
        float w0 = Wn[(i0 + 0) * K_ + o];
        float w1 = Wn[(i0 + 1) * K_ + o];
        float w2 = Wn[(i0 + 2) * K_ + o];
        float w3 = Wn[(i0 + 3) * K_ + o];
        #pragma unroll
        for (int bb = 0; bb < BG; bb++) {
            float4 xv = *(const float4*)&xs[bb][i0];
            acc[bb] += xv.x * w0 + xv.y * w1 + xv.z * w2 + xv.w * w3;
        }
    }
    #pragma unroll 8
    for (int bb = 0; bb < BG; bb++)
        g_xloc[((size_t)(b0 + bb) * N_ + n) * K_ + o] = acc[bb];
}

// ---------------- K4a: transpose + LN over N (kn2), 32 k per block ----------------
__global__ void k_trln(const float* __restrict__ kn2g, const float* __restrict__ kn2b) {
    int k0 = blockIdx.x * 32;
    int b  = blockIdx.y;
    int t  = threadIdx.x;
    __shared__ float tr[32][264];
    __shared__ float mm[32], rr[32];
    for (int q = t; q < 2048; q += 256) {
        int n = q >> 3, f = q & 7;
        float4 v = *(const float4*)&g_xloc[((size_t)b * N_ + n) * K_ + k0 + f * 4];
        tr[f * 4 + 0][n] = v.x; tr[f * 4 + 1][n] = v.y;
        tr[f * 4 + 2][n] = v.z; tr[f * 4 + 3][n] = v.w;
    }
    __syncthreads();
    int k = t >> 3, s = t & 7;
    float s1 = 0.f, s2 = 0.f;
    #pragma unroll 8
    for (int j = 0; j < 32; j++) {
        float v = tr[k][s + 8 * j];
        s1 += v; s2 += v * v;
    }
    #pragma unroll
    for (int off = 4; off > 0; off >>= 1) {
        s1 += __shfl_xor_sync(0xffffffffu, s1, off);
        s2 += __shfl_xor_sync(0xffffffffu, s2, off);
    }
    if (s == 0) {
        float m = s1 * (1.f / N_);
        float var = s2 * (1.f / N_) - m * m;
        mm[k] = m; rr[k] = rsqrtf(var + 1e-5f);
    }
    __syncthreads();
    int n2 = t;
    float gn = kn2g[n2], bn = kn2b[n2];
    #pragma unroll 4
    for (int kk = 0; kk < 32; kk++) {
        float v = (tr[kk][n2] - mm[kk]) * rr[kk] * gn + bn;
        g_xln[((size_t)b * K_ + k0 + kk) * N_ + n2] = v;
    }
}

// ---------------- K4b: x_global = x_ln @ A (32 k rows per block) ----------------
__global__ void k_xglob() {
    int kg = blockIdx.x;
    int b  = blockIdx.y;
    int t  = threadIdx.x;
    __shared__ float rows[32][256];
    for (int q = t; q < 2048; q += 256) {
        int kk = q >> 6, m4 = (q & 63) * 4;
        *(float4*)&rows[kk][m4] =
            *(const float4*)&g_xln[((size_t)b * K_ + kg * 32 + kk) * N_ + m4];
    }
    __syncthreads();
    float acc[32];
    #pragma unroll
    for (int kk = 0; kk < 32; kk++) acc[kk] = 0.f;
    int m = t;
    for (int nn = 0; nn < N_; nn += 4) {
        float a0 = g_A[(nn + 0) * N_ + m];
        float a1 = g_A[(nn + 1) * N_ + m];
        float a2 = g_A[(nn + 2) * N_ + m];
        float a3 = g_A[(nn + 3) * N_ + m];
        #pragma unroll
        for (int kk = 0; kk < 32; kk++) {
            float4 rv = *(const float4*)&rows[kk][nn];
            acc[kk] += rv.x * a0 + rv.y * a1 + rv.z * a2 + rv.w * a3;
        }
    }
    #pragma unroll 4
    for (int kk = 0; kk < 32; kk++)
        g_xglob[((size_t)b * K_ + kg * 32 + kk) * N_ + m] = acc[kk];
}

// ---------------- K5: mixed = LN( x + 0.5*rule + 0.5*kron , n1) ----------------
__global__ void k_mixed(const float* __restrict__ x,
                        const float* __restrict__ n1g, const float* __restrict__ n1b) {
    int row = blockIdx.x;
    int b = row >> 5, l = row & 31;
    int t = threadIdx.x;
    float v[4];
    float s1 = 0.f, s2 = 0.f;
    #pragma unroll
    for (int e = 0; e < 4; e++) {
        int d = t * 4 + e;
        float rule = x[((size_t)b * L_ + (d >> 5)) * D_ + l * 32 + (d & 31)];
        float kron = g_xglob[(size_t)row * D_ + d];
        float xv   = x[(size_t)row * D_ + d];
        float val = xv + 0.5f * rule + 0.5f * kron;
        v[e] = val; s1 += val; s2 += val * val;
    }
    blockReduce2_256(s1, s2);
    float m = s1 * (1.f / D_);
    float var = s2 * (1.f / D_) - m * m;
    float rs = rsqrtf(var + 1e-5f);
    #pragma unroll
    for (int e = 0; e < 4; e++) {
        int d = t * 4 + e;
        g_mixed[(size_t)row * D_ + d] = (v[e] - m) * rs * n1g[d] + n1b[d];
    }
}

// ---------------- cp.async pipelined fp16 tensor-core GEMM ----------------
// Stage layout (fp32 in smem): A 64 x 32 pad 40 words (10240 B) + B 32 x 128 pad 132 (16896 B)
#define STAGES   4
#define STG_AW   40
#define STG_BW   132
#define STG_AB   10240
#define STG_BYTES 27136
#define GEMM_SMEM (STAGES * STG_BYTES)

__global__ __launch_bounds__(256, 2) void k_gemm(const float* __restrict__ W0,
                                                 const float* __restrict__ W1,
                                                 int mode) {
    extern __shared__ float sm[];
    unsigned smem_u32 = (unsigned)__cvta_generic_to_shared(sm);

    int l   = blockIdx.x;
    int nt0 = blockIdx.y * 128;
    int t   = threadIdx.x;

    const float* Ap; long lda; int Kdim, width;
    const float* Bp; float* Op;
    if (mode == 0) {
        Ap = g_mixed + (size_t)l * D_;  lda = (long)L_ * D_;  Kdim = D_;  width = DFF;
        const float* Wsel = blockIdx.z ? W1 : W0;
        Bp = Wsel + (size_t)l * D_ * DFF + nt0;
        Op = (blockIdx.z ? g_U : g_G) + (size_t)l * DFF + nt0;
    } else {
        Ap = g_H + (size_t)l * DFF;     lda = (long)L_ * DFF; Kdim = DFF; width = D_;
        Bp = W0 + (size_t)l * DFF * D_ + nt0;
        Op = g_ffn + (size_t)l * D_ + nt0;
    }
    int nit = Kdim / 32;

    int lane = t & 31, wid = t >> 5;
    int g = lane >> 2, tg = lane & 3;
    int wm = (wid & 1) * 32;          // 2 warps over M=64
    int wn = (wid >> 1) * 32;         // 4 warps over N=128

    float acc[2][4][4];
    #pragma unroll
    for (int mt = 0; mt < 2; mt++)
        #pragma unroll
        for (int nt = 0; nt < 4; nt++)
            #pragma unroll
            for (int e = 0; e < 4; e++) acc[mt][nt][e] = 0.f;

    // producer: stage s -> buffer s % STAGES (always commits, maybe empty)
    auto issue = [&](int s) {
        if (s < nit) {
            int k0 = s * 32;
            unsigned base = smem_u32 + (s % STAGES) * STG_BYTES;
            #pragma unroll
            for (int i = 0; i < 2; i++) {
                int q = t + i * 256;
                int m = q >> 3, f4 = q & 7;
                unsigned dst = base + (unsigned)(m * STG_AW + f4 * 4) * 4u;
                const float* src = Ap + (size_t)m * lda + k0 + f4 * 4;
                asm volatile("cp.async.cg.shared.global [%0], [%1], 16;" :: "r"(dst), "l"(src));
            }
            #pragma unroll
            for (int i = 0; i < 4; i++) {
                int q = t + i * 256;
                int k = q >> 5, n4 = (q & 31) * 4;
                unsigned dst = base + STG_AB + (unsigned)(k * STG_BW + n4) * 4u;
                const float* src = Bp + (size_t)(k0 + k) * width + n4;
                asm volatile("cp.async.cg.shared.global [%0], [%1], 16;" :: "r"(dst), "l"(src));
            }
        }
        asm volatile("cp.async.commit_group;");
    };

    issue(0); issue(1); issue(2);

    for (int it = 0; it < nit; it++) {
        asm volatile("cp.async.wait_group 2;");
        __syncthreads();
        issue(it + 3);

        const float* Af = sm + (size_t)(it % STAGES) * (STG_BYTES / 4);
        const float* Bf = Af + STG_AB / 4;

        #pragma unroll
        for (int s = 0; s < 2; s++) {
            int kp0 = s * 8 + tg, kp1 = kp0 + 4;
            unsigned af[2][4];
            #pragma unroll
            for (int mt = 0; mt < 2; mt++) {
                int r0 = wm + mt * 16 + g, r1 = r0 + 8;
                float2 a00 = *(const float2*)&Af[r0 * STG_AW + 2 * kp0];
                float2 a10 = *(const float2*)&Af[r1 * STG_AW + 2 * kp0];
                float2 a01 = *(const float2*)&Af[r0 * STG_AW + 2 * kp1];
                float2 a11 = *(const float2*)&Af[r1 * STG_AW + 2 * kp1];
                af[mt][0] = pack16(a00.x, a00.y);
                af[mt][1] = pack16(a10.x, a10.y);
                af[mt][2] = pack16(a01.x, a01.y);
                af[mt][3] = pack16(a11.x, a11.y);
            }
            #pragma unroll
            for (int nt = 0; nt < 4; nt++) {
                int cn = wn + nt * 8 + g;
                unsigned b0 = pack16(Bf[(2 * kp0) * STG_BW + cn], Bf[(2 * kp0 + 1) * STG_BW + cn]);
                unsigned b1 = pack16(Bf[(2 * kp1) * STG_BW + cn], Bf[(2 * kp1 + 1) * STG_BW + cn]);
                mma16816(acc[0][nt], af[0], b0, b1);
                mma16816(acc[1][nt], af[1], b0, b1);
            }
        }
        __syncthreads();
    }

    long ostride = (long)L_ * width;
    #pragma unroll
    for (int mt = 0; mt < 2; mt++) {
        int r0 = wm + mt * 16 + g;
        #pragma unroll
        for (int nt = 0; nt < 4; nt++) {
            int c = wn + nt * 8 + tg * 2;
            float* p0 = Op + (size_t)r0 * ostride + c;
            float* p1 = Op + (size_t)(r0 + 8) * ostride + c;
            *(float2*)p0 = make_float2(acc[mt][nt][0], acc[mt][nt][1]);
            *(float2*)p1 = make_float2(acc[mt][nt][2], acc[mt][nt][3]);
        }
    }
}

// ---------------- K6b: H = silu(G) * U ----------------
__global__ void k_act() {
    int idx = blockIdx.x * 256 + threadIdx.x;
    float4 g = ((const float4*)g_G)[idx];
    float4 u = ((const float4*)g_U)[idx];
    float4 h;
    h.x = g.x / (1.f + expf(-g.x)) * u.x;
    h.y = g.y / (1.f + expf(-g.y)) * u.y;
    h.z = g.z / (1.f + expf(-g.z)) * u.z;
    h.w = g.w / (1.f + expf(-g.w)) * u.w;
    ((float4*)g_H)[idx] = h;
}

// ---------------- K8: out = LN(mixed+ffn, n2); y_out = y + ffn ----------------
__global__ void k_final(const float* __restrict__ y,
                        const float* __restrict__ n2g, const float* __restrict__ n2b,
                        float* __restrict__ out) {
    int row = blockIdx.x;
    int t = threadIdx.x;
    float v[4], fv[4];
    float s1 = 0.f, s2 = 0.f;
    #pragma unroll
    for (int e = 0; e < 4; e++) {
        int d = t * 4 + e;
        size_t idx = (size_t)row * D_ + d;
        float f = g_ffn[idx];
        float val = g_mixed[idx] + f;
        v[e] = val; fv[e] = f; s1 += val; s2 += val * val;
    }
    blockReduce2_256(s1, s2);
    float m = s1 * (1.f / D_);
    float var = s2 * (1.f / D_) - m * m;
    float rs = rsqrtf(var + 1e-5f);
    #pragma unroll
    for (int e = 0; e < 4; e++) {
        int d = t * 4 + e;
        size_t idx = (size_t)row * D_ + d;
        out[idx] = (v[e] - m) * rs * n2g[d] + n2b[d];
        out[(size_t)B_ * L_ * D_ + idx] = y[idx] + fv[e];
    }
}

// ---------------- launch ----------------
extern "C" void kernel_launch(void* const* d_in, const int* in_sizes, int n_in,
                              void* d_out, int out_size) {
    const float* x       = (const float*)d_in[0];
    const float* y       = (const float*)d_in[1];
    const float* A_log   = (const float*)d_in[2];
    const float* W_1     = (const float*)d_in[3];
    const float* W_V     = (const float*)d_in[4];
    const float* kn1_g   = (const float*)d_in[5];
    const float* kn1_b   = (const float*)d_in[6];
    const float* kn2_g   = (const float*)d_in[7];
    const float* kn2_b   = (const float*)d_in[8];
    const float* W_gate  = (const float*)d_in[9];
    const float* W_up    = (const float*)d_in[10];
    const float* W_down  = (const float*)d_in[11];
    const float* ny_g    = (const float*)d_in[12];
    const float* ny_b    = (const float*)d_in[13];
    const float* n1_g    = (const float*)d_in[14];
    const float* n1_b    = (const float*)d_in[15];
    const float* n2_g    = (const float*)d_in[16];
    const float* n2_b    = (const float*)d_in[17];
    float* out = (float*)d_out;

    static int smem_set = 0;
    if (!smem_set) {
        cudaFuncSetAttribute(k_gemm, cudaFuncAttributeMaxDynamicSharedMemorySize, GEMM_SMEM);
        smem_set = 1;
    }

    k_prepA<<<N_, 256>>>(A_log);
    k_prepW1<<<dim3(16, 8), 128>>>(W_1, W_V);
    k_prepW2<<<dim3(N_, 8), 128>>>();
    k_xr<<<B_ * L_, 256>>>(x, y, ny_g, ny_b, kn1_g, kn1_b);
    k_xlocal<<<dim3(N_, B_ / BG), 128>>>();
    k_trln<<<dim3(4, B_), 256>>>(kn2_g, kn2_b);
    k_xglob<<<dim3(4, B_), 256>>>();
    k_mixed<<<B_ * L_, 256>>>(x, n1_g, n1_b);
    k_gemm<<<dim3(L_, DFF / 128, 2), 256, GEMM_SMEM>>>(W_gate, W_up, 0);
    k_act<<<(B_ * L_ * DFF) / (256 * 4), 256>>>();
    k_gemm<<<dim3(L_, D_ / 128, 1), 256, GEMM_SMEM>>>(W_down, W_down, 1);
    k_final<<<B_ * L_, 256>>>(y, n2_g, n2_b, out);
}

// round 9
// speedup vs baseline: 1.6218x; 1.2719x over previous
#include <cuda_runtime.h>
#include <cuda_fp16.h>
#include <math.h>

#define B_   64
#define L_   32
#define D_   1024
#define DFF  2048
#define K_   128
#define N_   256

// ---------------- scratch (no allocations allowed) ----------------
__device__ float g_A[N_ * N_];
__device__ float g_W[N_ * K_ * K_];      // UNNORMALIZED Wl
__device__ float g_winv[N_ * K_];        // per (t,o) column inverse norm
__device__ float g_wpart[8][N_ * K_];
__device__ float g_xr[B_ * N_ * K_];
__device__ float g_xloc[B_ * N_ * K_];
__device__ float g_xln[B_ * K_ * N_];
__device__ float g_xglob[B_ * K_ * N_];
__device__ float g_mixed[B_ * L_ * D_];
__device__ float g_H[B_ * L_ * DFF];
__device__ float g_ffn[B_ * L_ * D_];

// ---------------- helpers ----------------
__device__ __forceinline__ void blockReduce2_256(float& s1, float& s2) {
    __shared__ float sh1[8], sh2[8];
    int t = threadIdx.x;
    #pragma unroll
    for (int o = 16; o > 0; o >>= 1) {
        s1 += __shfl_xor_sync(0xffffffffu, s1, o);
        s2 += __shfl_xor_sync(0xffffffffu, s2, o);
    }
    if ((t & 31) == 0) { sh1[t >> 5] = s1; sh2[t >> 5] = s2; }
    __syncthreads();
    float a = 0.f, b = 0.f;
    #pragma unroll
    for (int w = 0; w < 8; w++) { a += sh1[w]; b += sh2[w]; }
    s1 = a; s2 = b;
    __syncthreads();
}

__device__ __forceinline__ unsigned pack16(float x0, float x1) {
    unsigned h;
    asm("cvt.rn.f16x2.f32 %0, %1, %2;" : "=r"(h) : "f"(x1), "f"(x0));
    return h;
}

__device__ __forceinline__ void mma16816(float* c, const unsigned* a, unsigned b0, unsigned b1) {
    asm volatile(
        "mma.sync.aligned.m16n8k16.row.col.f32.f16.f16.f32 "
        "{%0,%1,%2,%3}, {%4,%5,%6,%7}, {%8,%9}, {%0,%1,%2,%3};"
        : "+f"(c[0]), "+f"(c[1]), "+f"(c[2]), "+f"(c[3])
        : "r"(a[0]), "r"(a[1]), "r"(a[2]), "r"(a[3]), "r"(b0), "r"(b1));
}

// ---------------- K0: A = A_logits / max(||col||, eps) ----------------
__global__ void k_prepA(const float* __restrict__ Al) {
    int j = blockIdx.x;
    int i = threadIdx.x;
    float v = Al[i * N_ + j];
    float s1 = v * v, s2 = 0.f;
    blockReduce2_256(s1, s2);
    float inv = 1.f / fmaxf(sqrtf(s1), 1e-12f);
    g_A[i * N_ + j] = v * inv;
}

// ---------------- prepW: unnormalized Wl + partial sumsq ----------------
__global__ void k_prepW1(const float* __restrict__ W1, const float* __restrict__ WV) {
    int tt = blockIdx.x;        // 16 t-tiles of 16
    int is = blockIdx.y;        // 8 i-slices of 16
    int o  = threadIdx.x;       // 128
    __shared__ float w1s[16][8];
    w1s[o >> 3][o & 7] = W1[(tt * 16 + (o >> 3)) * 8 + (o & 7)];
    __syncthreads();
    float ss[16];
    #pragma unroll
    for (int tl = 0; tl < 16; tl++) ss[tl] = 0.f;
    for (int ii = 0; ii < 16; ii++) {
        int i = is * 16 + ii;
        float wv[8];
        #pragma unroll
        for (int k = 0; k < 8; k++) wv[k] = WV[((size_t)k * K_ + i) * K_ + o];
        #pragma unroll
        for (int tl = 0; tl < 16; tl++) {
            float wl = 0.f;
            #pragma unroll
            for (int k = 0; k < 8; k++) wl += w1s[tl][k] * wv[k];
            ss[tl] += wl * wl;
            g_W[((size_t)(tt * 16 + tl) * K_ + i) * K_ + o] = wl;
        }
    }
    #pragma unroll
    for (int tl = 0; tl < 16; tl++)
        g_wpart[is][(tt * 16 + tl) * K_ + o] = ss[tl];
}

// tiny: just the inverse norms
__global__ void k_prepWinv() {
    int t = blockIdx.x;         // 256
    int o = threadIdx.x;        // 128
    float ss = 0.f;
    #pragma unroll
    for (int s = 0; s < 8; s++) ss += g_wpart[s][t * K_ + o];
    g_winv[t * K_ + o] = 1.f / fmaxf(sqrtf(ss), 1e-12f);
}

// ---------------- K2: xr = LN128( x + LN_D(y) ) ----------------
__global__ void k_xr(const float* __restrict__ x, const float* __restrict__ y,
                     const float* __restrict__ nyg, const float* __restrict__ nyb,
                     const float* __restrict__ kn1g, const float* __restrict__ kn1b) {
    int row = blockIdx.x;
    int t = threadIdx.x;
    const float* yr = y + (size_t)row * D_;
    const float* xp = x + (size_t)row * D_;
    float yv[4];
    float s1 = 0.f, s2 = 0.f;
    #pragma unroll
    for (int e = 0; e < 4; e++) {
        float v = yr[t * 4 + e];
        yv[e] = v; s1 += v; s2 += v * v;
    }
    blockReduce2_256(s1, s2);
    float m = s1 * (1.f / D_);
    float var = s2 * (1.f / D_) - m * m;
    float rs = rsqrtf(var + 1e-5f);
    float kin[4];
    float ls1 = 0.f, ls2 = 0.f;
    #pragma unroll
    for (int e = 0; e < 4; e++) {
        int d = t * 4 + e;
        float ny = (yv[e] - m) * rs * nyg[d] + nyb[d];
        float kv = xp[d] + ny;
        kin[e] = kv; ls1 += kv; ls2 += kv * kv;
    }
    #pragma unroll
    for (int o = 16; o > 0; o >>= 1) {
        ls1 += __shfl_xor_sync(0xffffffffu, ls1, o);
        ls2 += __shfl_xor_sync(0xffffffffu, ls2, o);
    }
    float lm = ls1 * (1.f / 128.f);
    float lv = ls2 * (1.f / 128.f) - lm * lm;
    float lrs = rsqrtf(lv + 1e-5f);
    #pragma unroll
    for (int e = 0; e < 4; e++) {
        int d = t * 4 + e;
        int i = d & 127;
        g_xr[(size_t)row * D_ + d] = (kin[e] - lm) * lrs * kn1g[i] + kn1b[i];
    }
}

// ---------------- K4a: transpose + LN over N (kn2), 32 k per block ----------------
__global__ void k_trln(const float* __restrict__ kn2g, const float* __restrict__ kn2b) {
    int k0 = blockIdx.x * 32;
    int b  = blockIdx.y;
    int t  = threadIdx.x;
    __shared__ float tr[32][264];
    __shared__ float mm[32], rr[32];
    for (int q = t; q < 2048; q += 256) {
        int n = q >> 3, f = q & 7;
        float4 v = *(const float4*)&g_xloc[((size_t)b * N_ + n) * K_ + k0 + f * 4];
        tr[f * 4 + 0][n] = v.x; tr[f * 4 + 1][n] = v.y;
        tr[f * 4 + 2][n] = v.z; tr[f * 4 + 3][n] = v.w;
    }
    __syncthreads();
    int k = t >> 3, s = t & 7;
    float s1 = 0.f, s2 = 0.f;
    #pragma unroll 8
    for (int j = 0; j < 32; j++) {
        float v = tr[k][s + 8 * j];
        s1 += v; s2 += v * v;
    }
    #pragma unroll
    for (int off = 4; off > 0; off >>= 1) {
        s1 += __shfl_xor_sync(0xffffffffu, s1, off);
        s2 += __shfl_xor_sync(0xffffffffu, s2, off);
    }
    if (s == 0) {
        float m = s1 * (1.f / N_);
        float var = s2 * (1.f / N_) - m * m;
        mm[k] = m; rr[k] = rsqrtf(var + 1e-5f);
    }
    __syncthreads();
    int n2 = t;
    float gn = kn2g[n2], bn = kn2b[n2];
    #pragma unroll 4
    for (int kk = 0; kk < 32; kk++) {
        float v = (tr[kk][n2] - mm[kk]) * rr[kk] * gn + bn;
        g_xln[((size_t)b * K_ + k0 + kk) * N_ + n2] = v;
    }
}

// ---------------- K5: mixed = LN( x + 0.5*rule + 0.5*kron , n1) ----------------
__global__ void k_mixed(const float* __restrict__ x,
                        const float* __restrict__ n1g, const float* __restrict__ n1b) {
    int row = blockIdx.x;
    int b = row >> 5, l = row & 31;
    int t = threadIdx.x;
    float v[4];
    float s1 = 0.f, s2 = 0.f;
    #pragma unroll
    for (int e = 0; e < 4; e++) {
        int d = t * 4 + e;
        float rule = x[((size_t)b * L_ + (d >> 5)) * D_ + l * 32 + (d & 31)];
        float kron = g_xglob[(size_t)row * D_ + d];
        float xv   = x[(size_t)row * D_ + d];
        float val = xv + 0.5f * rule + 0.5f * kron;
        v[e] = val; s1 += val; s2 += val * val;
    }
    blockReduce2_256(s1, s2);
    float m = s1 * (1.f / D_);
    float var = s2 * (1.f / D_) - m * m;
    float rs = rsqrtf(var + 1e-5f);
    #pragma unroll
    for (int e = 0; e < 4; e++) {
        int d = t * 4 + e;
        g_mixed[(size_t)row * D_ + d] = (v[e] - m) * rs * n1g[d] + n1b[d];
    }
}

// ---------------- generic cp.async pipelined fp16 tensor-core GEMM ----------------
// mode 1: down  A=g_H(l) [64x2048] @ W0(l)[2048x128tile] -> g_ffn
// mode 2: xglob A=g_xln rows [64x256] @ g_A [256x128tile] -> g_xglob
// mode 3: xloc  A=g_xr(:,n,:) [64x128] @ g_W(n)[128x128], scale by g_winv(n) -> g_xloc
#define STAGES   4
#define STG_AW   40
#define STG_BW   132
#define STG_AB   10240
#define STG_BYTES 27136
#define GEMM_SMEM (STAGES * STG_BYTES)

__global__ __launch_bounds__(256, 2) void k_gemm(const float* __restrict__ W0, int mode) {
    extern __shared__ float sm[];
    unsigned smem_u32 = (unsigned)__cvta_generic_to_shared(sm);

    int bx  = blockIdx.x;
    int nt0 = blockIdx.y * 128;
    int t   = threadIdx.x;

    const float* Ap; long lda, ostride; int Kdim, width;
    const float* Bp; float* Op; const float* sc = 0;
    if (mode == 1) {
        Ap = g_H + (size_t)bx * DFF;  lda = (long)L_ * DFF; Kdim = DFF; width = D_;
        Bp = W0 + (size_t)bx * DFF * D_ + nt0;
        Op = g_ffn + (size_t)bx * D_ + nt0;
        ostride = (long)L_ * D_;
    } else if (mode == 2) {
        Ap = g_xln + (size_t)bx * 64 * N_; lda = N_; Kdim = N_; width = N_;
        Bp = g_A + nt0;
        Op = g_xglob + (size_t)bx * 64 * N_ + nt0;
        ostride = N_;
    } else {
        Ap = g_xr + (size_t)bx * K_; lda = (long)N_ * K_; Kdim = K_; width = K_;
        Bp = g_W + (size_t)bx * K_ * K_;
        Op = g_xloc + (size_t)bx * K_;
        ostride = (long)N_ * K_;
        sc = g_winv + (size_t)bx * K_;
    }
    int nit = Kdim / 32;

    int lane = t & 31, wid = t >> 5;
    int g = lane >> 2, tg = lane & 3;
    int wm = (wid & 1) * 32;
    int wn = (wid >> 1) * 32;

    float acc[2][4][4];
    #pragma unroll
    for (int mt = 0; mt < 2; mt++)
        #pragma unroll
        for (int nt = 0; nt < 4; nt++)
            #pragma unroll
            for (int e = 0; e < 4; e++) acc[mt][nt][e] = 0.f;

    auto issue = [&](int s) {
        if (s < nit) {
            int k0 = s * 32;
            unsigned base = smem_u32 + (s % STAGES) * STG_BYTES;
            #pragma unroll
            for (int i = 0; i < 2; i++) {
                int q = t + i * 256;
                int m = q >> 3, f4 = q & 7;
                unsigned dst = base + (unsigned)(m * STG_AW + f4 * 4) * 4u;
                const float* src = Ap + (size_t)m * lda + k0 + f4 * 4;
                asm volatile("cp.async.cg.shared.global [%0], [%1], 16;" :: "r"(dst), "l"(src));
            }
            #pragma unroll
            for (int i = 0; i < 4; i++) {
                int q = t + i * 256;
                int k = q >> 5, n4 = (q & 31) * 4;
                unsigned dst = base + STG_AB + (unsigned)(k * STG_BW + n4) * 4u;
                const float* src = Bp + (size_t)(k0 + k) * width + n4;
                asm volatile("cp.async.cg.shared.global [%0], [%1], 16;" :: "r"(dst), "l"(src));
            }
        }
        asm volatile("cp.async.commit_group;");
    };

    issue(0); issue(1); issue(2);

    for (int it = 0; it < nit; it++) {
        asm volatile("cp.async.wait_group 2;");
        __syncthreads();
        issue(it + 3);

        const float* Af = sm + (size_t)(it % STAGES) * (STG_BYTES / 4);
        const float* Bf = Af + STG_AB / 4;

        #pragma unroll
        for (int s = 0; s < 2; s++) {
            int kp0 = s * 8 + tg, kp1 = kp0 + 4;
            unsigned af[2][4];
            #pragma unroll
            for (int mt = 0; mt < 2; mt++) {
                int r0 = wm + mt * 16 + g, r1 = r0 + 8;
                float2 a00 = *(const float2*)&Af[r0 * STG_AW + 2 * kp0];
                float2 a10 = *(const float2*)&Af[r1 * STG_AW + 2 * kp0];
                float2 a01 = *(const float2*)&Af[r0 * STG_AW + 2 * kp1];
                float2 a11 = *(const float2*)&Af[r1 * STG_AW + 2 * kp1];
                af[mt][0] = pack16(a00.x, a00.y);
                af[mt][1] = pack16(a10.x, a10.y);
                af[mt][2] = pack16(a01.x, a01.y);
                af[mt][3] = pack16(a11.x, a11.y);
            }
            #pragma unroll
            for (int nt = 0; nt < 4; nt++) {
                int cn = wn + nt * 8 + g;
                unsigned b0 = pack16(Bf[(2 * kp0) * STG_BW + cn], Bf[(2 * kp0 + 1) * STG_BW + cn]);
                unsigned b1 = pack16(Bf[(2 * kp1) * STG_BW + cn], Bf[(2 * kp1 + 1) * STG_BW + cn]);
                mma16816(acc[0][nt], af[0], b0, b1);
                mma16816(acc[1][nt], af[1], b0, b1);
            }
        }
        __syncthreads();
    }

    #pragma unroll
    for (int mt = 0; mt < 2; mt++) {
        int r0 = wm + mt * 16 + g;
        #pragma unroll
        for (int nt = 0; nt < 4; nt++) {
            int c = wn + nt * 8 + tg * 2;
            float v0 = acc[mt][nt][0], v1 = acc[mt][nt][1];
            float v2 = acc[mt][nt][2], v3 = acc[mt][nt][3];
            if (sc) {
                float s0 = sc[c], s1v = sc[c + 1];
                v0 *= s0; v1 *= s1v; v2 *= s0; v3 *= s1v;
            }
            float* p0 = Op + (size_t)r0 * ostride + c;
            float* p1 = Op + (size_t)(r0 + 8) * ostride + c;
            *(float2*)p0 = make_float2(v0, v1);
            *(float2*)p1 = make_float2(v2, v3);
        }
    }
}

// ---------------- fused gate+up+silu GEMM -> g_H ----------------
// B tile: 32 k x 132 pad; gate cols [0,64), up cols [64,128). Out tile 64 cols of DFF.
__global__ __launch_bounds__(256, 2) void k_gu(const float* __restrict__ Wg,
                                               const float* __restrict__ Wu) {
    extern __shared__ float sm[];
    unsigned smem_u32 = (unsigned)__cvta_generic_to_shared(sm);

    int l    = blockIdx.x;
    int ntg0 = blockIdx.y * 64;
    int t    = threadIdx.x;

    const float* Ap  = g_mixed + (size_t)l * D_;
    const long  lda  = (long)L_ * D_;
    const float* Bg  = Wg + (size_t)l * D_ * DFF + ntg0;
    const float* Bu  = Wu + (size_t)l * D_ * DFF + ntg0;
    float* Op        = g_H + (size_t)l * DFF + ntg0;
    const int nit    = D_ / 32;

    int lane = t & 31, wid = t >> 5;
    int g = lane >> 2, tg = lane & 3;
    int wm = (wid & 1) * 32;
    int wn = (wid >> 1) * 16;      // 4 warps over 64 gate cols

    float ag[2][2][4], au[2][2][4];
    #pragma unroll
    for (int mt = 0; mt < 2; mt++)
        #pragma unroll
        for (int nt = 0; nt < 2; nt++)
            #pragma unroll
            for (int e = 0; e < 4; e++) { ag[mt][nt][e] = 0.f; au[mt][nt][e] = 0.f; }

    auto issue = [&](int s) {
        if (s < nit) {
            int k0 = s * 32;
            unsigned base = smem_u32 + (s % STAGES) * STG_BYTES;
            #pragma unroll
            for (int i = 0; i < 2; i++) {
                int q = t + i * 256;
                int m = q >> 3, f4 = q & 7;
                unsigned dst = base + (unsigned)(m * STG_AW + f4 * 4) * 4u;
                const float* src = Ap + (size_t)m * lda + k0 + f4 * 4;
                asm volatile("cp.async.cg.shared.global [%0], [%1], 16;" :: "r"(dst), "l"(src));
            }
            // gate: 32k x 64n -> cols 0..63 ; up -> cols 64..127
            #pragma unroll
            for (int i = 0; i < 2; i++) {
                int q = t + i * 256;
                int k = q >> 4, n4 = (q & 15) * 4;
                unsigned dstg = base + STG_AB + (unsigned)(k * STG_BW + n4) * 4u;
                unsigned dstu = base + STG_AB + (unsigned)(k * STG_BW + 64 + n4) * 4u;
                const float* sg = Bg + (size_t)(k0 + k) * DFF + n4;
                const float* su = Bu + (size_t)(k0 + k) * DFF + n4;
                asm volatile("cp.async.cg.shared.global [%0], [%1], 16;" :: "r"(dstg), "l"(sg));
                asm volatile("cp.async.cg.shared.global [%0], [%1], 16;" :: "r"(dstu), "l"(su));
            }
        }
        asm volatile("cp.async.commit_group;");
    };

    issue(0); issue(1); issue(2);

    for (int it = 0; it < nit; it++) {
        asm volatile("cp.async.wait_group 2;");
        __syncthreads();
        issue(it + 3);

        const float* Af = sm + (size_t)(it % STAGES) * (STG_BYTES / 4);
        const float* Bf = Af + STG_AB / 4;

        #pragma unroll
        for (int s = 0; s < 2; s++) {
            int kp0 = s * 8 + tg, kp1 = kp0 + 4;
            unsigned af[2][4];
            #pragma unroll
            for (int mt = 0; mt < 2; mt++) {
                int r0 = wm + mt * 16 + g, r1 = r0 + 8;
                float2 a00 = *(const float2*)&Af[r0 * STG_AW + 2 * kp0];
                float2 a10 = *(const float2*)&Af[r1 * STG_AW + 2 * kp0];
                float2 a01 = *(const float2*)&Af[r0 * STG_AW + 2 * kp1];
                float2 a11 = *(const float2*)&Af[r1 * STG_AW + 2 * kp1];
                af[mt][0] = pack16(a00.x, a00.y);
                af[mt][1] = pack16(a10.x, a10.y);
                af[mt][2] = pack16(a01.x, a01.y);
                af[mt][3] = pack16(a11.x, a11.y);
            }
            #pragma unroll
            for (int nt = 0; nt < 2; nt++) {
                int cn = wn + nt * 8 + g;
                unsigned bg0 = pack16(Bf[(2 * kp0) * STG_BW + cn], Bf[(2 * kp0 + 1) * STG_BW + cn]);
                unsigned bg1 = pack16(Bf[(2 * kp1) * STG_BW + cn], Bf[(2 * kp1 + 1) * STG_BW + cn]);
                unsigned bu0 = pack16(Bf[(2 * kp0) * STG_BW + 64 + cn], Bf[(2 * kp0 + 1) * STG_BW + 64 + cn]);
                unsigned bu1 = pack16(Bf[(2 * kp1) * STG_BW + 64 + cn], Bf[(2 * kp1 + 1) * STG_BW + 64 + cn]);
                mma16816(ag[0][nt], af[0], bg0, bg1);
                mma16816(ag[1][nt], af[1], bg0, bg1);
                mma16816(au[0][nt], af[0], bu0, bu1);
                mma16816(au[1][nt], af[1], bu0, bu1);
            }
        }
        __syncthreads();
    }

    const long ostride = (long)L_ * DFF;
    #pragma unroll
    for (int mt = 0; mt < 2; mt++) {
        int r0 = wm + mt * 16 + g;
        #pragma unroll
        for (int nt = 0; nt < 2; nt++) {
            int c = wn + nt * 8 + tg * 2;
            float h0 = ag[mt][nt][0] / (1.f + expf(-ag[mt][nt][0])) * au[mt][nt][0];
            float h1 = ag[mt][nt][1] / (1.f + expf(-ag[mt][nt][1])) * au[mt][nt][1];
            float h2 = ag[mt][nt][2] / (1.f + expf(-ag[mt][nt][2])) * au[mt][nt][2];
            float h3 = ag[mt][nt][3] / (1.f + expf(-ag[mt][nt][3])) * au[mt][nt][3];
            float* p0 = Op + (size_t)r0 * ostride + c;
            float* p1 = Op + (size_t)(r0 + 8) * ostride + c;
            *(float2*)p0 = make_float2(h0, h1);
            *(float2*)p1 = make_float2(h2, h3);
        }
    }
}

// ---------------- K8: out = LN(mixed+ffn, n2); y_out = y + ffn ----------------
__global__ void k_final(const float* __restrict__ y,
                        const float* __restrict__ n2g, const float* __restrict__ n2b,
                        float* __restrict__ out) {
    int row = blockIdx.x;
    int t = threadIdx.x;
    float v[4], fv[4];
    float s1 = 0.f, s2 = 0.f;
    #pragma unroll
    for (int e = 0; e < 4; e++) {
        int d = t * 4 + e;
        size_t idx = (size_t)row * D_ + d;
        float f = g_ffn[idx];
        float val = g_mixed[idx] + f;
        v[e] = val; fv[e] = f; s1 += val; s2 += val * val;
    }
    blockReduce2_256(s1, s2);
    float m = s1 * (1.f / D_);
    float var = s2 * (1.f / D_) - m * m;
    float rs = rsqrtf(var + 1e-5f);
    #pragma unroll
    for (int e = 0; e < 4; e++) {
        int d = t * 4 + e;
        size_t idx = (size_t)row * D_ + d;
        out[idx] = (v[e] - m) * rs * n2g[d] + n2b[d];
        out[(size_t)B_ * L_ * D_ + idx] = y[idx] + fv[e];
    }
}

// ---------------- launch ----------------
extern "C" void kernel_launch(void* const* d_in, const int* in_sizes, int n_in,
                              void* d_out, int out_size) {
    const float* x       = (const float*)d_in[0];
    const float* y       = (const float*)d_in[1];
    const float* A_log   = (const float*)d_in[2];
    const float* W_1     = (const float*)d_in[3];
    const float* W_V     = (const float*)d_in[4];
    const float* kn1_g   = (const float*)d_in[5];
    const float* kn1_b   = (const float*)d_in[6];
    const float* kn2_g   = (const float*)d_in[7];
    const float* kn2_b   = (const float*)d_in[8];
    const float* W_gate  = (const float*)d_in[9];
    const float* W_up    = (const float*)d_in[10];
    const float* W_down  = (const float*)d_in[11];
    const float* ny_g    = (const float*)d_in[12];
    const float* ny_b    = (const float*)d_in[13];
    const float* n1_g    = (const float*)d_in[14];
    const float* n1_b    = (const float*)d_in[15];
    const float* n2_g    = (const float*)d_in[16];
    const float* n2_b    = (const float*)d_in[17];
    float* out = (float*)d_out;

    static int smem_set = 0;
    if (!smem_set) {
        cudaFuncSetAttribute(k_gemm, cudaFuncAttributeMaxDynamicSharedMemorySize, GEMM_SMEM);
        cudaFuncSetAttribute(k_gu,   cudaFuncAttributeMaxDynamicSharedMemorySize, GEMM_SMEM);
        smem_set = 1;
    }

    k_prepA<<<N_, 256>>>(A_log);
    k_prepW1<<<dim3(16, 8), 128>>>(W_1, W_V);
    k_prepWinv<<<N_, 128>>>();
    k_xr<<<B_ * L_, 256>>>(x, y, ny_g, ny_b, kn1_g, kn1_b);
    k_gemm<<<dim3(N_, 1), 256, GEMM_SMEM>>>(nullptr, 3);          // x_local
    k_trln<<<dim3(4, B_), 256>>>(kn2_g, kn2_b);
    k_gemm<<<dim3(128, 2), 256, GEMM_SMEM>>>(nullptr, 2);         // x_global
    k_mixed<<<B_ * L_, 256>>>(x, n1_g, n1_b);
    k_gu<<<dim3(L_, DFF / 64), 256, GEMM_SMEM>>>(W_gate, W_up);   // gate+up+silu
    k_gemm<<<dim3(L_, D_ / 128), 256, GEMM_SMEM>>>(W_down, 1);    // down
    k_final<<<B_ * L_, 256>>>(y, n2_g, n2_b, out);
}